// round 8
// baseline (speedup 1.0000x reference)
#include <cuda_runtime.h>
#include <cuda_fp16.h>
#include <math.h>
#include <stdint.h>

#define PLANE 3145728            // 3072 * 1024
#define WELEMS 17825792          // 17 * 1024 * 1024

// ---------------- device scratch --------------------------------------------
__device__ float g_Y[PLANE];                 // pre-projection Y of current layer
__device__ float g_xt[17 * PLANE];           // xs[l] planes (fp32)
__device__ __half g_hX[2][PLANE];            // ping-pong fp16 X
__device__ __half g_hW[WELEMS];              // fp16 weights (W0 at 0, Ws at 1..16)

// ---------------- helpers -----------------------------------------------------
static __device__ __forceinline__ uint32_t smem_u32(const void* p) {
    return (uint32_t)__cvta_generic_to_shared(p);
}
static __device__ __forceinline__ void ldsm4(uint32_t* r, uint32_t addr) {
    asm volatile("ldmatrix.sync.aligned.m8n8.x4.shared.b16 {%0,%1,%2,%3}, [%4];"
        : "=r"(r[0]), "=r"(r[1]), "=r"(r[2]), "=r"(r[3]) : "r"(addr));
}
static __device__ __forceinline__ void mma16816(float* c, const uint32_t* a,
                                                uint32_t b0, uint32_t b1) {
    asm volatile("mma.sync.aligned.m16n8k16.row.col.f32.f16.f16.f32 "
        "{%0,%1,%2,%3}, {%4,%5,%6,%7}, {%8,%9}, {%0,%1,%2,%3};"
        : "+f"(c[0]), "+f"(c[1]), "+f"(c[2]), "+f"(c[3])
        : "r"(a[0]), "r"(a[1]), "r"(a[2]), "r"(a[3]), "r"(b0), "r"(b1));
}

// ---------------- weight conversion (fp16) -----------------------------------
__global__ void wconv_kernel(const float* __restrict__ W0, const float* __restrict__ Ws) {
    size_t i = (size_t)blockIdx.x * 256 + threadIdx.x;
    if (i >= (size_t)WELEMS) return;
    float v = (i < 1048576) ? W0[i] : Ws[i - 1048576];
    g_hW[i] = __float2half_rn(v);
}

// ---------------- prep: fp16 of input (ch2 transposed) -----------------------
__global__ void prep_kernel(const float* __restrict__ Xin) {
    int idx = blockIdx.x * 256 + threadIdx.x;
    if (idx >= PLANE) return;
    int d  = idx & 1023;
    int bc = idx >> 10;
    int c  = bc % 3;
    float v;
    if (c == 2) {
        int b = bc / 3;
        int dim = d >> 4, k = d & 15;
        v = Xin[((size_t)(b * 3 + 2)) * 1024 + k * 64 + dim];
    } else {
        v = Xin[idx];
    }
    g_hX[0][idx] = __float2half_rn(v);
}

// ---------------- fp16 mma.sync GEMM + fused epilogue ------------------------
// Tile 96x128 (256 CTAs), K-chunk 32, 3-stage cp.async, 8 warps (2M x 4N).
#define MAT_STRIDE_B 80                  // bytes per smem row (pad, conflict-free)
#define A_BYTES (96 * MAT_STRIDE_B)      // 7680
#define B_BYTES (128 * MAT_STRIDE_B)     // 10240
#define STAGE_BYTES (A_BYTES + B_BYTES)  // 17920
#define SMEM_TOTAL_G (3 * STAGE_BYTES)   // 53760

__global__ __launch_bounds__(256, 2) void tgemm_kernel(
    const float* __restrict__ bias, const float* __restrict__ hp, int layer)
{
    extern __shared__ __align__(16) char smem[];
    uint32_t sb = smem_u32(smem);

    int tid = threadIdx.x;
    int wid = tid >> 5, lane = tid & 31;
    int bx = blockIdx.x;
    int m0 = (bx >> 3) * 96;
    int n0 = (bx & 7) * 128;

    int par = layer & 1;
    const __half* srcA = g_hX[par] + (size_t)m0 * 1024;
    const __half* srcB = g_hW + (size_t)layer * 1048576 + (size_t)n0 * 1024;

    float acc[3][4][4];
#pragma unroll
    for (int i = 0; i < 3; i++)
#pragma unroll
        for (int j = 0; j < 4; j++)
#pragma unroll
            for (int k = 0; k < 4; k++) acc[i][j][k] = 0.f;

    auto issue = [&](int c, int st) {
#pragma unroll
        for (int u = 0; u < 4; u++) {
            int unit = tid + u * 256;        // 0..1023, use 0..895
            if (unit < 896) {
                uint32_t dst;
                const __half* gp;
                if (unit < 384) {            // A: 96 rows x 4 segs
                    int row = unit >> 2, seg = unit & 3;
                    dst = sb + st * STAGE_BYTES + row * MAT_STRIDE_B + seg * 16;
                    gp = srcA + (size_t)row * 1024 + c * 32 + seg * 8;
                } else {                     // B: 128 rows x 4 segs
                    int t = unit - 384;
                    int row = t >> 2, seg = t & 3;
                    dst = sb + st * STAGE_BYTES + A_BYTES + row * MAT_STRIDE_B + seg * 16;
                    gp = srcB + (size_t)row * 1024 + c * 32 + seg * 8;
                }
                asm volatile("cp.async.cg.shared.global [%0], [%1], 16;"
                    :: "r"(dst), "l"(gp));
            }
        }
        asm volatile("cp.async.commit_group;" ::: "memory");
    };

    issue(0, 0);
    issue(1, 1);

    int mw = (wid >> 2) * 48, nw = (wid & 3) * 32;
    int lrow = (lane & 7) + ((lane >> 3) & 1) * 8;
    int lcolB = ((lane >> 4) * 8) * 2;

    for (int c = 0; c < 32; c++) {
        int st = c % 3;
        if (c + 2 < 32) {
            issue(c + 2, (c + 2) % 3);
            asm volatile("cp.async.wait_group 2;" ::: "memory");
        } else if (c + 1 < 32) {
            asm volatile("cp.async.wait_group 1;" ::: "memory");
        } else {
            asm volatile("cp.async.wait_group 0;" ::: "memory");
        }
        __syncthreads();

        uint32_t base = sb + st * STAGE_BYTES;
#pragma unroll
        for (int ks = 0; ks < 2; ks++) {
            int colb = ks * 32 + lcolB;
            uint32_t bh[2][4];
#pragma unroll
            for (int nb = 0; nb < 2; nb++)
                ldsm4(bh[nb], base + A_BYTES +
                              (nw + nb * 16 + lrow) * MAT_STRIDE_B + colb);
#pragma unroll
            for (int ma = 0; ma < 3; ma++) {
                uint32_t ah[4];
                ldsm4(ah, base + (mw + ma * 16 + lrow) * MAT_STRIDE_B + colb);
#pragma unroll
                for (int na = 0; na < 4; na++) {
                    int nb = na >> 1, hi = na & 1;
                    mma16816(acc[ma][na], ah, bh[nb][hi], bh[nb][2 + hi]);
                }
            }
        }
        __syncthreads();
    }

    // ---- fused epilogue
    float hv = 0.f;
    const float* Xprev = nullptr;
    if (layer > 0) { hv = *hp; Xprev = g_xt + (size_t)(layer - 1) * PLANE; }
    float* PL = g_xt + (size_t)layer * PLANE;
    int opar = (layer + 1) & 1;
    int g = lane >> 2, t2 = (lane & 3) * 2;

#pragma unroll
    for (int ma = 0; ma < 3; ma++) {
#pragma unroll
        for (int na = 0; na < 4; na++) {
            int n = n0 + nw + na * 8 + t2;
            float2 b2 = make_float2(0.f, 0.f);
            if (layer > 0) b2 = *(const float2*)(bias + n);
#pragma unroll
            for (int hh = 0; hh < 2; hh++) {
                int m = m0 + mw + ma * 16 + g + hh * 8;
                float cx = acc[ma][na][hh * 2], cy = acc[ma][na][hh * 2 + 1];
                float2 y;
                if (layer > 0) {
                    float2 xo = *(const float2*)(Xprev + (size_t)m * 1024 + n);
                    y.x = xo.x + hv * fmaxf(cx + b2.x, 0.f);
                    y.y = xo.y + hv * fmaxf(cy + b2.y, 0.f);
                } else {
                    y.x = cx; y.y = cy;
                }
                if (m % 3 == 1) {          // S channel: no projection
                    *(float2*)(PL + (size_t)m * 1024 + n) = y;
                    __half2 h2;
                    h2.x = __float2half_rn(y.x);
                    h2.y = __float2half_rn(y.y);
                    *(__half2*)(&g_hX[opar][(size_t)m * 1024 + n]) = h2;
                } else {                   // U/V channels: polar input only
                    *(float2*)(g_Y + (size_t)m * 1024 + n) = y;
                }
            }
        }
    }
}

// ---------------- polar projection: warp PAIR per 64x16 matrix ---------------
// Each warp handles 32 rows of A (load/Gram-partial/final U/stores); the cheap
// 16x16 NS iterations run duplicated per warp on private smem copies.
#define PNM 4      // matrices per block (8 warps)
__global__ __launch_bounds__(256) void polar_kernel(int plane, int nspecial,
                                                    int nclassic, float ca_s,
                                                    float cb_s, int opar) {
    __shared__ float AsP[PNM][16][68];           // A col-major, shared by pair
    __shared__ float MsP[PNM][2][3][16][20];     // per-warp Y,Z,T copies

    int wwid = threadIdx.x >> 5;       // 0..7
    int widx = wwid >> 1, half = wwid & 1;
    int lane = threadIdx.x & 31;
    int idx = blockIdx.x * PNM + widx;
    int b = idx >> 1, ch = (idx & 1) * 2;

    const float* src = g_Y + (size_t)(b * 3 + ch) * 1024;
    size_t doff = (size_t)(b * 3 + ch) * 1024;
    float* dst = g_xt + (size_t)plane * PLANE + doff;

    float (*A)[68]  = AsP[widx];
    float (*Ym)[20] = MsP[widx][half][0];
    float (*Zm)[20] = MsP[widx][half][1];
    float (*Tm)[20] = MsP[widx][half][2];
    float (*TmP)[20] = MsP[widx][half ^ 1][2];   // partner's Gram partial

    int r = half * 32 + lane;          // this thread's A row
    // load own row (16 floats) into col-major smem
#pragma unroll
    for (int qq = 0; qq < 4; qq++) {
        float4 v = *(const float4*)(src + r * 16 + qq * 4);
        A[qq * 4 + 0][r] = v.x; A[qq * 4 + 1][r] = v.y;
        A[qq * 4 + 2][r] = v.z; A[qq * 4 + 3][r] = v.w;
    }
    __syncwarp();

    // Gram partial over own 32 rows: lane tile rows {i0,i0+1} x cols j0..j0+3
    int i0 = (lane >> 2) * 2, j0 = (lane & 3) * 4;
    float g0[4] = {0, 0, 0, 0}, g1[4] = {0, 0, 0, 0};
    int rbase = half * 32;
#pragma unroll
    for (int rr = 0; rr < 32; rr += 4) {
        float4 a0 = *(const float4*)&A[i0][rbase + rr];
        float4 a1 = *(const float4*)&A[i0 + 1][rbase + rr];
#pragma unroll
        for (int t = 0; t < 4; t++) {
            float4 aj = *(const float4*)&A[j0 + t][rbase + rr];
            g0[t] += a0.x * aj.x + a0.y * aj.y + a0.z * aj.z + a0.w * aj.w;
            g1[t] += a1.x * aj.x + a1.y * aj.y + a1.z * aj.z + a1.w * aj.w;
        }
    }
    *(float4*)&Tm[i0][j0]     = make_float4(g0[0], g0[1], g0[2], g0[3]);
    *(float4*)&Tm[i0 + 1][j0] = make_float4(g1[0], g1[1], g1[2], g1[3]);
    __syncthreads();

    // full G = own + partner partial
    {
        float4 p0 = *(const float4*)&TmP[i0][j0];
        float4 p1 = *(const float4*)&TmP[i0 + 1][j0];
        g0[0] += p0.x; g0[1] += p0.y; g0[2] += p0.z; g0[3] += p0.w;
        g1[0] += p1.x; g1[1] += p1.y; g1[2] += p1.z; g1[3] += p1.w;
    }
    *(float4*)&Ym[i0][j0]     = make_float4(g0[0], g0[1], g0[2], g0[3]);
    *(float4*)&Ym[i0 + 1][j0] = make_float4(g1[0], g1[1], g1[2], g1[3]);
    __syncwarp();

    // s = ||G||_inf
    float rs = 0.f;
    if (lane < 16) {
#pragma unroll
        for (int j = 0; j < 16; j++) rs += fabsf(Ym[lane][j]);
    }
#pragma unroll
    for (int off = 16; off; off >>= 1)
        rs = fmaxf(rs, __shfl_xor_sync(0xffffffffu, rs, off));
    float invs = 1.0f / rs;

#pragma unroll
    for (int t = 0; t < 4; t++) { g0[t] *= invs; g1[t] *= invs; }
    *(float4*)&Ym[i0][j0]     = make_float4(g0[0], g0[1], g0[2], g0[3]);
    *(float4*)&Ym[i0 + 1][j0] = make_float4(g1[0], g1[1], g1[2], g1[3]);
    *(float4*)&Zm[i0][j0] = make_float4(i0 == j0 ? 1.f : 0.f, i0 == j0 + 1 ? 1.f : 0.f,
                                        i0 == j0 + 2 ? 1.f : 0.f, i0 == j0 + 3 ? 1.f : 0.f);
    *(float4*)&Zm[i0 + 1][j0] = make_float4(i0 + 1 == j0 ? 1.f : 0.f, i0 + 1 == j0 + 1 ? 1.f : 0.f,
                                            i0 + 1 == j0 + 2 ? 1.f : 0.f, i0 + 1 == j0 + 3 ? 1.f : 0.f);
    __syncwarp();

    int ntot = nspecial + nclassic;
    for (int it = 0; it < ntot; it++) {
        float ca = (it < nspecial) ? ca_s : 1.5f;
        float cb = (it < nspecial) ? cb_s : -0.5f;
        float t0[4] = {0, 0, 0, 0}, t1[4] = {0, 0, 0, 0};
#pragma unroll
        for (int k = 0; k < 16; k++) {
            float z0 = Zm[i0][k], z1 = Zm[i0 + 1][k];
            float4 y4 = *(const float4*)&Ym[k][j0];
            t0[0] += z0 * y4.x; t0[1] += z0 * y4.y; t0[2] += z0 * y4.z; t0[3] += z0 * y4.w;
            t1[0] += z1 * y4.x; t1[1] += z1 * y4.y; t1[2] += z1 * y4.z; t1[3] += z1 * y4.w;
        }
#pragma unroll
        for (int t = 0; t < 4; t++) {
            t0[t] = ((i0     == j0 + t) ? ca : 0.f) + cb * t0[t];
            t1[t] = ((i0 + 1 == j0 + t) ? ca : 0.f) + cb * t1[t];
        }
        *(float4*)&Tm[i0][j0]     = make_float4(t0[0], t0[1], t0[2], t0[3]);
        *(float4*)&Tm[i0 + 1][j0] = make_float4(t1[0], t1[1], t1[2], t1[3]);
        __syncwarp();

        float yn0[4] = {0, 0, 0, 0}, yn1[4] = {0, 0, 0, 0};
        float zn0[4] = {0, 0, 0, 0}, zn1[4] = {0, 0, 0, 0};
#pragma unroll
        for (int k = 0; k < 16; k++) {
            float4 t4 = *(const float4*)&Tm[k][j0];
            float ya = Ym[i0][k], yb = Ym[i0 + 1][k];
            yn0[0] += ya * t4.x; yn0[1] += ya * t4.y; yn0[2] += ya * t4.z; yn0[3] += ya * t4.w;
            yn1[0] += yb * t4.x; yn1[1] += yb * t4.y; yn1[2] += yb * t4.z; yn1[3] += yb * t4.w;
            float4 z4 = *(const float4*)&Zm[k][j0];
            float ta = Tm[i0][k], tb = Tm[i0 + 1][k];
            zn0[0] += ta * z4.x; zn0[1] += ta * z4.y; zn0[2] += ta * z4.z; zn0[3] += ta * z4.w;
            zn1[0] += tb * z4.x; zn1[1] += tb * z4.y; zn1[2] += tb * z4.z; zn1[3] += tb * z4.w;
        }
        __syncwarp();
        *(float4*)&Ym[i0][j0]     = make_float4(yn0[0], yn0[1], yn0[2], yn0[3]);
        *(float4*)&Ym[i0 + 1][j0] = make_float4(yn1[0], yn1[1], yn1[2], yn1[3]);
        *(float4*)&Zm[i0][j0]     = make_float4(zn0[0], zn0[1], zn0[2], zn0[3]);
        *(float4*)&Zm[i0 + 1][j0] = make_float4(zn1[0], zn1[1], zn1[2], zn1[3]);
        __syncwarp();
    }

    // U row r = A[:,r] dot Z columns, scaled by s^-1/2
    float isq = rsqrtf(rs);
    float u[16];
#pragma unroll
    for (int c = 0; c < 16; c++) u[c] = 0.f;
#pragma unroll
    for (int k = 0; k < 16; k++) {
        float a = A[k][r];
#pragma unroll
        for (int cq = 0; cq < 4; cq++) {
            float4 z4 = *(const float4*)&Zm[k][cq * 4];
            u[cq * 4 + 0] += a * z4.x; u[cq * 4 + 1] += a * z4.y;
            u[cq * 4 + 2] += a * z4.z; u[cq * 4 + 3] += a * z4.w;
        }
    }
#pragma unroll
    for (int c = 0; c < 16; c++) u[c] *= isq;

    __syncthreads();   // A no longer needed; reuse as pack buffer

    // fp32: pack own half (rows half*32..+31 = floats half*512..+511), store coalesced
    float* pk = (float*)&A[0][0] + half * 512;
#pragma unroll
    for (int cq = 0; cq < 4; cq++)
        *(float4*)&pk[lane * 16 + cq * 4] = make_float4(u[cq * 4], u[cq * 4 + 1],
                                                        u[cq * 4 + 2], u[cq * 4 + 3]);
    __syncwarp();
    {
        float4* gd = (float4*)(dst + half * 512);
        const float4* ps = (const float4*)pk;
#pragma unroll
        for (int j = 0; j < 4; j++) gd[lane + 32 * j] = ps[lane + 32 * j];
    }
    __syncwarp();

    // fp16: pack own half (256 uint32), store coalesced
    uint32_t* pu = (uint32_t*)pk;
#pragma unroll
    for (int cq = 0; cq < 8; cq++) {
        __half2 h2;
        h2.x = __float2half_rn(u[2 * cq]);
        h2.y = __float2half_rn(u[2 * cq + 1]);
        pu[lane * 8 + cq] = *(uint32_t*)&h2;
    }
    __syncwarp();
    {
        uint32_t* gd = (uint32_t*)(g_hX[opar] + doff) + half * 256;
#pragma unroll
        for (int j = 0; j < 8; j++) gd[lane + 32 * j] = pu[lane + 32 * j];
    }
}

// ---------------- X_transformed transpose ------------------------------------
__global__ void xt_kernel(float* __restrict__ out) {
    __shared__ float tile[256][18];
    int base = blockIdx.x * 256;
    int tid = threadIdx.x;
#pragma unroll
    for (int l = 0; l < 17; l++)
        tile[tid][l] = g_xt[(size_t)l * PLANE + base + tid];
    __syncthreads();
    float* o = out + (size_t)base * 17;
    for (int i = tid; i < 256 * 17; i += 256)
        o[i] = tile[i / 17][i % 17];
}

// ---------------- reconstruct + classify + softmax ----------------------------
__global__ __launch_bounds__(128) void classify_kernel(
    const float* __restrict__ Wc, const float* __restrict__ bc,
    float* __restrict__ out, int off_log)
{
    __shared__ float sU[1024], sS[256], sV[1024], sT[1024];
    __shared__ float sZ[4096];
    __shared__ float red[10 * 136];
    __shared__ float slog[10];

    int b = blockIdx.x, tid = threadIdx.x;
    const float* base = g_xt + (size_t)16 * PLANE + (size_t)b * 3 * 1024;

    for (int i = tid; i < 1024; i += 128) { sU[i] = base[i]; sV[i] = base[2048 + i]; }
    for (int i = tid; i < 256; i += 128) sS[i] = base[1024 + i];
    __syncthreads();

    for (int e = tid; e < 1024; e += 128) {
        int r = e >> 4, c = e & 15;
        float sum = 0.f;
#pragma unroll
        for (int k = 0; k < 16; k++) sum += sU[r * 16 + k] * sS[k * 16 + c];
        sT[e] = sum;
    }
    __syncthreads();

    for (int e = tid; e < 4096; e += 128) {
        int r = e >> 6, qn = e & 63;
        float sum = 0.f;
#pragma unroll
        for (int c = 0; c < 16; c++) sum += sT[r * 16 + c] * sV[qn * 16 + c];
        sZ[e] = sum;
    }
    __syncthreads();

    float acc[10];
#pragma unroll
    for (int n = 0; n < 10; n++) acc[n] = 0.f;
    for (int e = tid; e < 4096; e += 128) {
        float z = sZ[e];
#pragma unroll
        for (int n = 0; n < 10; n++) acc[n] += z * Wc[n * 4096 + e];
    }
#pragma unroll
    for (int n = 0; n < 10; n++) red[n * 136 + tid] = acc[n];
    __syncthreads();
    if (tid < 10) {
        float s = bc[tid];
        for (int j = 0; j < 128; j++) s += red[tid * 136 + j];
        slog[tid] = s;
    }
    __syncthreads();
    if (tid == 0) {
        float mx = slog[0];
        for (int n = 1; n < 10; n++) mx = fmaxf(mx, slog[n]);
        float ex[10]; float se = 0.f;
        for (int n = 0; n < 10; n++) { ex[n] = expf(slog[n] - mx); se += ex[n]; }
        float inv = 1.f / se;
        for (int n = 0; n < 10; n++) {
            out[b * 10 + n] = ex[n] * inv;
            if (off_log >= 0) out[off_log + b * 10 + n] = slog[n];
        }
    }
}

// ---------------- launch ------------------------------------------------------
extern "C" void kernel_launch(void* const* d_in, const int* in_sizes, int n_in,
                              void* d_out, int out_size) {
    const float* X  = (const float*)d_in[0];
    const float* h  = (const float*)d_in[1];
    const float* W0 = (const float*)d_in[2];
    const float* Ws = (const float*)d_in[3];
    const float* bs = (const float*)d_in[4];
    const float* Wc = (const float*)d_in[5];
    const float* bc = (const float*)d_in[6];
    float* out = (float*)d_out;

    int off_log = -1, off_xt = -1;
    if (out_size >= 10240 + 10240 + 53477376) { off_log = 10240; off_xt = 20480; }
    else if (out_size == 10240 + 53477376)    { off_xt = 10240; }
    else if (out_size >= 20480)               { off_log = 10240; }

    cudaFuncSetAttribute(tgemm_kernel, cudaFuncAttributeMaxDynamicSharedMemorySize,
                         SMEM_TOTAL_G);

    wconv_kernel<<<WELEMS / 256, 256>>>(W0, Ws);
    prep_kernel<<<PLANE / 256, 256>>>(X);

    tgemm_kernel<<<256, 256, SMEM_TOTAL_G>>>(nullptr, h, 0);
    polar_kernel<<<512, 256>>>(0, 4, 6, 2.4f, -1.4f, 1);   // layer 0: 4 agg + 6 classic
    for (int l = 1; l <= 16; l++) {
        tgemm_kernel<<<256, 256, SMEM_TOTAL_G>>>(bs + (size_t)(l - 1) * 1024, h, l);
        polar_kernel<<<512, 256>>>(l, 1, 3, 1.9f, -0.9f, (l + 1) & 1);  // 1 tuned + 3 classic
    }

    if (off_xt >= 0)
        xt_kernel<<<PLANE / 256, 256>>>(out + off_xt);
    classify_kernel<<<1024, 128>>>(Wc, bc, out, off_log);
}

// round 9
// speedup vs baseline: 1.1784x; 1.1784x over previous
#include <cuda_runtime.h>
#include <cuda_fp16.h>
#include <math.h>
#include <stdint.h>

#define PLANE 3145728            // 3072 * 1024
#define WELEMS 17825792          // 17 * 1024 * 1024

// ---------------- device scratch --------------------------------------------
__device__ float g_Y[PLANE];                 // pre-projection Y of current layer
__device__ float g_xt[17 * PLANE];           // xs[l] planes (fp32)
__device__ __half g_hX[2][PLANE];            // ping-pong fp16 X
__device__ __half g_hW[WELEMS];              // fp16 weights (W0 at 0, Ws at 1..16)

// ---------------- helpers -----------------------------------------------------
static __device__ __forceinline__ uint32_t smem_u32(const void* p) {
    return (uint32_t)__cvta_generic_to_shared(p);
}
static __device__ __forceinline__ void ldsm4(uint32_t* r, uint32_t addr) {
    asm volatile("ldmatrix.sync.aligned.m8n8.x4.shared.b16 {%0,%1,%2,%3}, [%4];"
        : "=r"(r[0]), "=r"(r[1]), "=r"(r[2]), "=r"(r[3]) : "r"(addr));
}
static __device__ __forceinline__ void mma16816(float* c, const uint32_t* a,
                                                uint32_t b0, uint32_t b1) {
    asm volatile("mma.sync.aligned.m16n8k16.row.col.f32.f16.f16.f32 "
        "{%0,%1,%2,%3}, {%4,%5,%6,%7}, {%8,%9}, {%0,%1,%2,%3};"
        : "+f"(c[0]), "+f"(c[1]), "+f"(c[2]), "+f"(c[3])
        : "r"(a[0]), "r"(a[1]), "r"(a[2]), "r"(a[3]), "r"(b0), "r"(b1));
}

// ---------------- weight conversion (fp16) -----------------------------------
__global__ void wconv_kernel(const float* __restrict__ W0, const float* __restrict__ Ws) {
    size_t i = (size_t)blockIdx.x * 256 + threadIdx.x;
    if (i >= (size_t)WELEMS) return;
    float v = (i < 1048576) ? W0[i] : Ws[i - 1048576];
    g_hW[i] = __float2half_rn(v);
}

// ---------------- prep: fp16 of input (ch2 transposed) -----------------------
__global__ void prep_kernel(const float* __restrict__ Xin) {
    int idx = blockIdx.x * 256 + threadIdx.x;
    if (idx >= PLANE) return;
    int d  = idx & 1023;
    int bc = idx >> 10;
    int c  = bc % 3;
    float v;
    if (c == 2) {
        int b = bc / 3;
        int dim = d >> 4, k = d & 15;
        v = Xin[((size_t)(b * 3 + 2)) * 1024 + k * 64 + dim];
    } else {
        v = Xin[idx];
    }
    g_hX[0][idx] = __float2half_rn(v);
}

// ---------------- fp16 mma.sync GEMM + fused epilogue ------------------------
// Tile 96x128 (256 CTAs), K-chunk 32, 3-stage cp.async, 8 warps (2M x 4N).
#define MAT_STRIDE_B 80                  // bytes per smem row (pad, conflict-free)
#define A_BYTES (96 * MAT_STRIDE_B)      // 7680
#define B_BYTES (128 * MAT_STRIDE_B)     // 10240
#define STAGE_BYTES (A_BYTES + B_BYTES)  // 17920
#define SMEM_TOTAL_G (3 * STAGE_BYTES)   // 53760

__global__ __launch_bounds__(256, 2) void tgemm_kernel(
    const float* __restrict__ bias, const float* __restrict__ hp, int layer)
{
    extern __shared__ __align__(16) char smem[];
    uint32_t sb = smem_u32(smem);

    int tid = threadIdx.x;
    int wid = tid >> 5, lane = tid & 31;
    int bx = blockIdx.x;
    int m0 = (bx >> 3) * 96;
    int n0 = (bx & 7) * 128;

    int par = layer & 1;
    const __half* srcA = g_hX[par] + (size_t)m0 * 1024;
    const __half* srcB = g_hW + (size_t)layer * 1048576 + (size_t)n0 * 1024;

    float acc[3][4][4];
#pragma unroll
    for (int i = 0; i < 3; i++)
#pragma unroll
        for (int j = 0; j < 4; j++)
#pragma unroll
            for (int k = 0; k < 4; k++) acc[i][j][k] = 0.f;

    auto issue = [&](int c, int st) {
#pragma unroll
        for (int u = 0; u < 4; u++) {
            int unit = tid + u * 256;        // 0..1023, use 0..895
            if (unit < 896) {
                uint32_t dst;
                const __half* gp;
                if (unit < 384) {            // A: 96 rows x 4 segs
                    int row = unit >> 2, seg = unit & 3;
                    dst = sb + st * STAGE_BYTES + row * MAT_STRIDE_B + seg * 16;
                    gp = srcA + (size_t)row * 1024 + c * 32 + seg * 8;
                } else {                     // B: 128 rows x 4 segs
                    int t = unit - 384;
                    int row = t >> 2, seg = t & 3;
                    dst = sb + st * STAGE_BYTES + A_BYTES + row * MAT_STRIDE_B + seg * 16;
                    gp = srcB + (size_t)row * 1024 + c * 32 + seg * 8;
                }
                asm volatile("cp.async.cg.shared.global [%0], [%1], 16;"
                    :: "r"(dst), "l"(gp));
            }
        }
        asm volatile("cp.async.commit_group;" ::: "memory");
    };

    issue(0, 0);
    issue(1, 1);

    int mw = (wid >> 2) * 48, nw = (wid & 3) * 32;
    int lrow = (lane & 7) + ((lane >> 3) & 1) * 8;
    int lcolB = ((lane >> 4) * 8) * 2;

    for (int c = 0; c < 32; c++) {
        int st = c % 3;
        if (c + 2 < 32) {
            issue(c + 2, (c + 2) % 3);
            asm volatile("cp.async.wait_group 2;" ::: "memory");
        } else if (c + 1 < 32) {
            asm volatile("cp.async.wait_group 1;" ::: "memory");
        } else {
            asm volatile("cp.async.wait_group 0;" ::: "memory");
        }
        __syncthreads();

        uint32_t base = sb + st * STAGE_BYTES;
#pragma unroll
        for (int ks = 0; ks < 2; ks++) {
            int colb = ks * 32 + lcolB;
            uint32_t bh[2][4];
#pragma unroll
            for (int nb = 0; nb < 2; nb++)
                ldsm4(bh[nb], base + A_BYTES +
                              (nw + nb * 16 + lrow) * MAT_STRIDE_B + colb);
#pragma unroll
            for (int ma = 0; ma < 3; ma++) {
                uint32_t ah[4];
                ldsm4(ah, base + (mw + ma * 16 + lrow) * MAT_STRIDE_B + colb);
#pragma unroll
                for (int na = 0; na < 4; na++) {
                    int nb = na >> 1, hi = na & 1;
                    mma16816(acc[ma][na], ah, bh[nb][hi], bh[nb][2 + hi]);
                }
            }
        }
        __syncthreads();
    }

    // ---- fused epilogue
    float hv = 0.f;
    const float* Xprev = nullptr;
    if (layer > 0) { hv = *hp; Xprev = g_xt + (size_t)(layer - 1) * PLANE; }
    float* PL = g_xt + (size_t)layer * PLANE;
    int opar = (layer + 1) & 1;
    int g = lane >> 2, t2 = (lane & 3) * 2;

#pragma unroll
    for (int ma = 0; ma < 3; ma++) {
#pragma unroll
        for (int na = 0; na < 4; na++) {
            int n = n0 + nw + na * 8 + t2;
            float2 b2 = make_float2(0.f, 0.f);
            if (layer > 0) b2 = *(const float2*)(bias + n);
#pragma unroll
            for (int hh = 0; hh < 2; hh++) {
                int m = m0 + mw + ma * 16 + g + hh * 8;
                float cx = acc[ma][na][hh * 2], cy = acc[ma][na][hh * 2 + 1];
                float2 y;
                if (layer > 0) {
                    float2 xo = *(const float2*)(Xprev + (size_t)m * 1024 + n);
                    y.x = xo.x + hv * fmaxf(cx + b2.x, 0.f);
                    y.y = xo.y + hv * fmaxf(cy + b2.y, 0.f);
                } else {
                    y.x = cx; y.y = cy;
                }
                if (m % 3 == 1) {          // S channel: no projection
                    *(float2*)(PL + (size_t)m * 1024 + n) = y;
                    __half2 h2;
                    h2.x = __float2half_rn(y.x);
                    h2.y = __float2half_rn(y.y);
                    *(__half2*)(&g_hX[opar][(size_t)m * 1024 + n]) = h2;
                } else {                   // U/V channels: polar input only
                    *(float2*)(g_Y + (size_t)m * 1024 + n) = y;
                }
            }
        }
    }
}

// ---------------- polar projection (tuned Newton-Schulz on 16x16 Gram) -------
// One warp per 64x16 matrix. Own A rows retained in registers for the U phase.
#define PNW 4
__global__ __launch_bounds__(128) void polar_kernel(int plane, int nspecial,
                                                    int nclassic, float ca_s,
                                                    float cb_s, int opar) {
    __shared__ float AsP[PNW][16][68];
    __shared__ float MsP[PNW][3][16][20];

    int w = threadIdx.x >> 5, lane = threadIdx.x & 31;
    int idx = blockIdx.x * PNW + w;
    int b = idx >> 1, ch = (idx & 1) * 2;

    const float* src = g_Y + (size_t)(b * 3 + ch) * 1024;
    size_t doff = (size_t)(b * 3 + ch) * 1024;
    float* dst = g_xt + (size_t)plane * PLANE + doff;

    float (*A)[68]  = AsP[w];
    float (*Ym)[20] = MsP[w][0];
    float (*Zm)[20] = MsP[w][1];
    float (*Tm)[20] = MsP[w][2];

    int r0 = lane * 2;
    float a0r[16], a1r[16];            // own two A rows kept in registers
#pragma unroll
    for (int qq = 0; qq < 4; qq++) {
        float4 v0 = *(const float4*)(src + r0 * 16 + qq * 4);
        float4 v1 = *(const float4*)(src + (r0 + 1) * 16 + qq * 4);
        a0r[qq * 4 + 0] = v0.x; a0r[qq * 4 + 1] = v0.y;
        a0r[qq * 4 + 2] = v0.z; a0r[qq * 4 + 3] = v0.w;
        a1r[qq * 4 + 0] = v1.x; a1r[qq * 4 + 1] = v1.y;
        a1r[qq * 4 + 2] = v1.z; a1r[qq * 4 + 3] = v1.w;
        A[qq * 4 + 0][r0] = v0.x; A[qq * 4 + 1][r0] = v0.y;
        A[qq * 4 + 2][r0] = v0.z; A[qq * 4 + 3][r0] = v0.w;
        A[qq * 4 + 0][r0 + 1] = v1.x; A[qq * 4 + 1][r0 + 1] = v1.y;
        A[qq * 4 + 2][r0 + 1] = v1.z; A[qq * 4 + 3][r0 + 1] = v1.w;
    }
    __syncwarp();

    int i0 = (lane >> 2) * 2, j0 = (lane & 3) * 4;
    float g0[4] = {0, 0, 0, 0}, g1[4] = {0, 0, 0, 0};
#pragma unroll
    for (int r = 0; r < 64; r += 4) {
        float4 a0 = *(const float4*)&A[i0][r];
        float4 a1 = *(const float4*)&A[i0 + 1][r];
#pragma unroll
        for (int t = 0; t < 4; t++) {
            float4 aj = *(const float4*)&A[j0 + t][r];
            g0[t] += a0.x * aj.x + a0.y * aj.y + a0.z * aj.z + a0.w * aj.w;
            g1[t] += a1.x * aj.x + a1.y * aj.y + a1.z * aj.z + a1.w * aj.w;
        }
    }
    *(float4*)&Ym[i0][j0]     = make_float4(g0[0], g0[1], g0[2], g0[3]);
    *(float4*)&Ym[i0 + 1][j0] = make_float4(g1[0], g1[1], g1[2], g1[3]);
    __syncwarp();

    float rs = 0.f;
    if (lane < 16) {
#pragma unroll
        for (int j = 0; j < 16; j++) rs += fabsf(Ym[lane][j]);
    }
#pragma unroll
    for (int off = 16; off; off >>= 1)
        rs = fmaxf(rs, __shfl_xor_sync(0xffffffffu, rs, off));
    float invs = 1.0f / rs;

#pragma unroll
    for (int t = 0; t < 4; t++) { g0[t] *= invs; g1[t] *= invs; }
    *(float4*)&Ym[i0][j0]     = make_float4(g0[0], g0[1], g0[2], g0[3]);
    *(float4*)&Ym[i0 + 1][j0] = make_float4(g1[0], g1[1], g1[2], g1[3]);
    *(float4*)&Zm[i0][j0] = make_float4(i0 == j0 ? 1.f : 0.f, i0 == j0 + 1 ? 1.f : 0.f,
                                        i0 == j0 + 2 ? 1.f : 0.f, i0 == j0 + 3 ? 1.f : 0.f);
    *(float4*)&Zm[i0 + 1][j0] = make_float4(i0 + 1 == j0 ? 1.f : 0.f, i0 + 1 == j0 + 1 ? 1.f : 0.f,
                                            i0 + 1 == j0 + 2 ? 1.f : 0.f, i0 + 1 == j0 + 3 ? 1.f : 0.f);
    __syncwarp();

    int ntot = nspecial + nclassic;
    for (int it = 0; it < ntot; it++) {
        float ca = (it < nspecial) ? ca_s : 1.5f;
        float cb = (it < nspecial) ? cb_s : -0.5f;
        float t0[4] = {0, 0, 0, 0}, t1[4] = {0, 0, 0, 0};
#pragma unroll
        for (int k = 0; k < 16; k++) {
            float z0 = Zm[i0][k], z1 = Zm[i0 + 1][k];
            float4 y4 = *(const float4*)&Ym[k][j0];
            t0[0] += z0 * y4.x; t0[1] += z0 * y4.y; t0[2] += z0 * y4.z; t0[3] += z0 * y4.w;
            t1[0] += z1 * y4.x; t1[1] += z1 * y4.y; t1[2] += z1 * y4.z; t1[3] += z1 * y4.w;
        }
#pragma unroll
        for (int t = 0; t < 4; t++) {
            t0[t] = ((i0     == j0 + t) ? ca : 0.f) + cb * t0[t];
            t1[t] = ((i0 + 1 == j0 + t) ? ca : 0.f) + cb * t1[t];
        }
        *(float4*)&Tm[i0][j0]     = make_float4(t0[0], t0[1], t0[2], t0[3]);
        *(float4*)&Tm[i0 + 1][j0] = make_float4(t1[0], t1[1], t1[2], t1[3]);
        __syncwarp();

        float yn0[4] = {0, 0, 0, 0}, yn1[4] = {0, 0, 0, 0};
        float zn0[4] = {0, 0, 0, 0}, zn1[4] = {0, 0, 0, 0};
#pragma unroll
        for (int k = 0; k < 16; k++) {
            float4 t4 = *(const float4*)&Tm[k][j0];
            float ya = Ym[i0][k], yb = Ym[i0 + 1][k];
            yn0[0] += ya * t4.x; yn0[1] += ya * t4.y; yn0[2] += ya * t4.z; yn0[3] += ya * t4.w;
            yn1[0] += yb * t4.x; yn1[1] += yb * t4.y; yn1[2] += yb * t4.z; yn1[3] += yb * t4.w;
            float4 z4 = *(const float4*)&Zm[k][j0];
            float ta = Tm[i0][k], tb = Tm[i0 + 1][k];
            zn0[0] += ta * z4.x; zn0[1] += ta * z4.y; zn0[2] += ta * z4.z; zn0[3] += ta * z4.w;
            zn1[0] += tb * z4.x; zn1[1] += tb * z4.y; zn1[2] += tb * z4.z; zn1[3] += tb * z4.w;
        }
        __syncwarp();
        *(float4*)&Ym[i0][j0]     = make_float4(yn0[0], yn0[1], yn0[2], yn0[3]);
        *(float4*)&Ym[i0 + 1][j0] = make_float4(yn1[0], yn1[1], yn1[2], yn1[3]);
        *(float4*)&Zm[i0][j0]     = make_float4(zn0[0], zn0[1], zn0[2], zn0[3]);
        *(float4*)&Zm[i0 + 1][j0] = make_float4(zn1[0], zn1[1], zn1[2], zn1[3]);
        __syncwarp();
    }

    // U = A * Z * s^(-1/2); own A rows come from registers
    float isq = rsqrtf(rs);
    float u0[16], u1[16];
#pragma unroll
    for (int c = 0; c < 16; c++) { u0[c] = 0.f; u1[c] = 0.f; }
#pragma unroll
    for (int k = 0; k < 16; k++) {
        float a0 = a0r[k], a1 = a1r[k];
#pragma unroll
        for (int cq = 0; cq < 4; cq++) {
            float4 z4 = *(const float4*)&Zm[k][cq * 4];
            u0[cq * 4 + 0] += a0 * z4.x; u0[cq * 4 + 1] += a0 * z4.y;
            u0[cq * 4 + 2] += a0 * z4.z; u0[cq * 4 + 3] += a0 * z4.w;
            u1[cq * 4 + 0] += a1 * z4.x; u1[cq * 4 + 1] += a1 * z4.y;
            u1[cq * 4 + 2] += a1 * z4.z; u1[cq * 4 + 3] += a1 * z4.w;
        }
    }
#pragma unroll
    for (int c = 0; c < 16; c++) { u0[c] *= isq; u1[c] *= isq; }

    // fp32 U out
#pragma unroll
    for (int cq = 0; cq < 4; cq++) {
        *(float4*)(dst + r0 * 16 + cq * 4) =
            make_float4(u0[cq * 4], u0[cq * 4 + 1], u0[cq * 4 + 2], u0[cq * 4 + 3]);
        *(float4*)(dst + (r0 + 1) * 16 + cq * 4) =
            make_float4(u1[cq * 4], u1[cq * 4 + 1], u1[cq * 4 + 2], u1[cq * 4 + 3]);
    }

    // fp16 out: pack via smem for coalesced writes
    uint32_t phi[16];
#pragma unroll
    for (int row2 = 0; row2 < 2; row2++) {
        float* u = row2 ? u1 : u0;
#pragma unroll
        for (int cq = 0; cq < 8; cq++) {
            __half2 hp2;
            hp2.x = __float2half_rn(u[2 * cq]);
            hp2.y = __float2half_rn(u[2 * cq + 1]);
            phi[row2 * 8 + cq] = *(uint32_t*)&hp2;
        }
    }
    __syncwarp();
    uint32_t* pk = (uint32_t*)&A[0][0];
#pragma unroll
    for (int row2 = 0; row2 < 2; row2++)
#pragma unroll
        for (int cq = 0; cq < 8; cq++) pk[(r0 + row2) * 8 + cq] = phi[row2 * 8 + cq];
    __syncwarp();
    {
        uint32_t* gd = (uint32_t*)(g_hX[opar] + doff);
#pragma unroll
        for (int i = 0; i < 16; i++) gd[lane + 32 * i] = pk[lane + 32 * i];
    }
}

// ---------------- X_transformed transpose ------------------------------------
__global__ void xt_kernel(float* __restrict__ out) {
    __shared__ float tile[256][18];
    int base = blockIdx.x * 256;
    int tid = threadIdx.x;
#pragma unroll
    for (int l = 0; l < 17; l++)
        tile[tid][l] = g_xt[(size_t)l * PLANE + base + tid];
    __syncthreads();
    float* o = out + (size_t)base * 17;
    for (int i = tid; i < 256 * 17; i += 256)
        o[i] = tile[i / 17][i % 17];
}

// ---------------- reconstruct + classify + softmax ----------------------------
__global__ __launch_bounds__(128) void classify_kernel(
    const float* __restrict__ Wc, const float* __restrict__ bc,
    float* __restrict__ out, int off_log)
{
    __shared__ float sU[1024], sS[256], sV[1024], sT[1024];
    __shared__ float sZ[4096];
    __shared__ float red[10 * 136];
    __shared__ float slog[10];

    int b = blockIdx.x, tid = threadIdx.x;
    const float* base = g_xt + (size_t)16 * PLANE + (size_t)b * 3 * 1024;

    for (int i = tid; i < 1024; i += 128) { sU[i] = base[i]; sV[i] = base[2048 + i]; }
    for (int i = tid; i < 256; i += 128) sS[i] = base[1024 + i];
    __syncthreads();

    for (int e = tid; e < 1024; e += 128) {
        int r = e >> 4, c = e & 15;
        float sum = 0.f;
#pragma unroll
        for (int k = 0; k < 16; k++) sum += sU[r * 16 + k] * sS[k * 16 + c];
        sT[e] = sum;
    }
    __syncthreads();

    for (int e = tid; e < 4096; e += 128) {
        int r = e >> 6, qn = e & 63;
        float sum = 0.f;
#pragma unroll
        for (int c = 0; c < 16; c++) sum += sT[r * 16 + c] * sV[qn * 16 + c];
        sZ[e] = sum;
    }
    __syncthreads();

    float acc[10];
#pragma unroll
    for (int n = 0; n < 10; n++) acc[n] = 0.f;
    for (int e = tid; e < 4096; e += 128) {
        float z = sZ[e];
#pragma unroll
        for (int n = 0; n < 10; n++) acc[n] += z * Wc[n * 4096 + e];
    }
#pragma unroll
    for (int n = 0; n < 10; n++) red[n * 136 + tid] = acc[n];
    __syncthreads();
    if (tid < 10) {
        float s = bc[tid];
        for (int j = 0; j < 128; j++) s += red[tid * 136 + j];
        slog[tid] = s;
    }
    __syncthreads();
    if (tid == 0) {
        float mx = slog[0];
        for (int n = 1; n < 10; n++) mx = fmaxf(mx, slog[n]);
        float ex[10]; float se = 0.f;
        for (int n = 0; n < 10; n++) { ex[n] = expf(slog[n] - mx); se += ex[n]; }
        float inv = 1.f / se;
        for (int n = 0; n < 10; n++) {
            out[b * 10 + n] = ex[n] * inv;
            if (off_log >= 0) out[off_log + b * 10 + n] = slog[n];
        }
    }
}

// ---------------- launch ------------------------------------------------------
extern "C" void kernel_launch(void* const* d_in, const int* in_sizes, int n_in,
                              void* d_out, int out_size) {
    const float* X  = (const float*)d_in[0];
    const float* h  = (const float*)d_in[1];
    const float* W0 = (const float*)d_in[2];
    const float* Ws = (const float*)d_in[3];
    const float* bs = (const float*)d_in[4];
    const float* Wc = (const float*)d_in[5];
    const float* bc = (const float*)d_in[6];
    float* out = (float*)d_out;

    int off_log = -1, off_xt = -1;
    if (out_size >= 10240 + 10240 + 53477376) { off_log = 10240; off_xt = 20480; }
    else if (out_size == 10240 + 53477376)    { off_xt = 10240; }
    else if (out_size >= 20480)               { off_log = 10240; }

    cudaFuncSetAttribute(tgemm_kernel, cudaFuncAttributeMaxDynamicSharedMemorySize,
                         SMEM_TOTAL_G);

    wconv_kernel<<<WELEMS / 256, 256>>>(W0, Ws);
    prep_kernel<<<PLANE / 256, 256>>>(X);

    tgemm_kernel<<<256, 256, SMEM_TOTAL_G>>>(nullptr, h, 0);
    polar_kernel<<<512, 128>>>(0, 4, 5, 2.4f, -1.4f, 1);   // layer 0: 4 agg + 5 classic
    for (int l = 1; l <= 16; l++) {
        tgemm_kernel<<<256, 256, SMEM_TOTAL_G>>>(bs + (size_t)(l - 1) * 1024, h, l);
        polar_kernel<<<512, 128>>>(l, 1, 2, 1.9f, -0.9f, (l + 1) & 1);  // 1 tuned + 2 classic
    }

    if (off_xt >= 0)
        xt_kernel<<<PLANE / 256, 256>>>(out + off_xt);
    classify_kernel<<<1024, 128>>>(Wc, bc, out, off_log);
}

// round 10
// speedup vs baseline: 1.2304x; 1.0441x over previous
#include <cuda_runtime.h>
#include <cuda_fp16.h>
#include <math.h>
#include <stdint.h>

#define PLANE 3145728            // 3072 * 1024
#define WELEMS 17825792          // 17 * 1024 * 1024

// ---------------- device scratch --------------------------------------------
__device__ float g_Y[PLANE];                 // pre-projection Y of current layer
__device__ float g_xt[17 * PLANE];           // xs[l] planes (fp32)
__device__ __half g_hX[2][PLANE];            // ping-pong fp16 X
__device__ __half g_hW[WELEMS];              // fp16 weights (W0 at 0, Ws at 1..16)

// ---------------- helpers -----------------------------------------------------
static __device__ __forceinline__ uint32_t smem_u32(const void* p) {
    return (uint32_t)__cvta_generic_to_shared(p);
}
static __device__ __forceinline__ void ldsm4(uint32_t* r, uint32_t addr) {
    asm volatile("ldmatrix.sync.aligned.m8n8.x4.shared.b16 {%0,%1,%2,%3}, [%4];"
        : "=r"(r[0]), "=r"(r[1]), "=r"(r[2]), "=r"(r[3]) : "r"(addr));
}
static __device__ __forceinline__ void mma16816(float* c, const uint32_t* a,
                                                uint32_t b0, uint32_t b1) {
    asm volatile("mma.sync.aligned.m16n8k16.row.col.f32.f16.f16.f32 "
        "{%0,%1,%2,%3}, {%4,%5,%6,%7}, {%8,%9}, {%0,%1,%2,%3};"
        : "+f"(c[0]), "+f"(c[1]), "+f"(c[2]), "+f"(c[3])
        : "r"(a[0]), "r"(a[1]), "r"(a[2]), "r"(a[3]), "r"(b0), "r"(b1));
}

// ---------------- weight conversion (fp16) -----------------------------------
__global__ void wconv_kernel(const float* __restrict__ W0, const float* __restrict__ Ws) {
    size_t i = (size_t)blockIdx.x * 256 + threadIdx.x;
    if (i >= (size_t)WELEMS) return;
    float v = (i < 1048576) ? W0[i] : Ws[i - 1048576];
    g_hW[i] = __float2half_rn(v);
}

// ---------------- prep: fp16 of input (ch2 transposed) -----------------------
__global__ void prep_kernel(const float* __restrict__ Xin) {
    int idx = blockIdx.x * 256 + threadIdx.x;
    if (idx >= PLANE) return;
    int d  = idx & 1023;
    int bc = idx >> 10;
    int c  = bc % 3;
    float v;
    if (c == 2) {
        int b = bc / 3;
        int dim = d >> 4, k = d & 15;
        v = Xin[((size_t)(b * 3 + 2)) * 1024 + k * 64 + dim];
    } else {
        v = Xin[idx];
    }
    g_hX[0][idx] = __float2half_rn(v);
}

// ---------------- fp16 mma.sync GEMM + fused epilogue ------------------------
// Tile 96x128 (256 CTAs), K-chunk 32, 3-stage cp.async, 8 warps (2M x 4N).
// Single __syncthreads per k-iter (wait -> sync -> issue(c+2) -> compute).
#define MAT_STRIDE_B 80                  // bytes per smem row (pad, conflict-free)
#define A_BYTES (96 * MAT_STRIDE_B)      // 7680
#define B_BYTES (128 * MAT_STRIDE_B)     // 10240
#define STAGE_BYTES (A_BYTES + B_BYTES)  // 17920
#define SMEM_TOTAL_G (3 * STAGE_BYTES)   // 53760

__global__ __launch_bounds__(256, 2) void tgemm_kernel(
    const float* __restrict__ bias, const float* __restrict__ hp, int layer)
{
    extern __shared__ __align__(16) char smem[];
    uint32_t sb = smem_u32(smem);

    int tid = threadIdx.x;
    int wid = tid >> 5, lane = tid & 31;
    int bx = blockIdx.x;
    int m0 = (bx >> 3) * 96;
    int n0 = (bx & 7) * 128;

    int par = layer & 1;
    const __half* srcA = g_hX[par] + (size_t)m0 * 1024;
    const __half* srcB = g_hW + (size_t)layer * 1048576 + (size_t)n0 * 1024;

    float acc[3][4][4];
#pragma unroll
    for (int i = 0; i < 3; i++)
#pragma unroll
        for (int j = 0; j < 4; j++)
#pragma unroll
            for (int k = 0; k < 4; k++) acc[i][j][k] = 0.f;

    auto issue = [&](int c, int st) {
#pragma unroll
        for (int u = 0; u < 4; u++) {
            int unit = tid + u * 256;        // 0..1023, use 0..895
            if (unit < 896) {
                uint32_t dst;
                const __half* gp;
                if (unit < 384) {            // A: 96 rows x 4 segs
                    int row = unit >> 2, seg = unit & 3;
                    dst = sb + st * STAGE_BYTES + row * MAT_STRIDE_B + seg * 16;
                    gp = srcA + (size_t)row * 1024 + c * 32 + seg * 8;
                } else {                     // B: 128 rows x 4 segs
                    int t = unit - 384;
                    int row = t >> 2, seg = t & 3;
                    dst = sb + st * STAGE_BYTES + A_BYTES + row * MAT_STRIDE_B + seg * 16;
                    gp = srcB + (size_t)row * 1024 + c * 32 + seg * 8;
                }
                asm volatile("cp.async.cg.shared.global [%0], [%1], 16;"
                    :: "r"(dst), "l"(gp));
            }
        }
        asm volatile("cp.async.commit_group;" ::: "memory");
    };

    issue(0, 0);
    issue(1, 1);

    int mw = (wid >> 2) * 48, nw = (wid & 3) * 32;
    int lrow = (lane & 7) + ((lane >> 3) & 1) * 8;
    int lcolB = ((lane >> 4) * 8) * 2;

    for (int c = 0; c < 32; c++) {
        int st = c % 3;
        if (c < 31) {
            asm volatile("cp.async.wait_group 1;" ::: "memory");
        } else {
            asm volatile("cp.async.wait_group 0;" ::: "memory");
        }
        __syncthreads();
        if (c + 2 < 32) issue(c + 2, (c + 2) % 3);

        uint32_t base = sb + st * STAGE_BYTES;
#pragma unroll
        for (int ks = 0; ks < 2; ks++) {
            int colb = ks * 32 + lcolB;
            uint32_t bh[2][4];
#pragma unroll
            for (int nb = 0; nb < 2; nb++)
                ldsm4(bh[nb], base + A_BYTES +
                              (nw + nb * 16 + lrow) * MAT_STRIDE_B + colb);
#pragma unroll
            for (int ma = 0; ma < 3; ma++) {
                uint32_t ah[4];
                ldsm4(ah, base + (mw + ma * 16 + lrow) * MAT_STRIDE_B + colb);
#pragma unroll
                for (int na = 0; na < 4; na++) {
                    int nb = na >> 1, hi = na & 1;
                    mma16816(acc[ma][na], ah, bh[nb][hi], bh[nb][2 + hi]);
                }
            }
        }
    }

    // ---- fused epilogue
    float hv = 0.f;
    const float* Xprev = nullptr;
    if (layer > 0) { hv = *hp; Xprev = g_xt + (size_t)(layer - 1) * PLANE; }
    float* PL = g_xt + (size_t)layer * PLANE;
    int opar = (layer + 1) & 1;
    int g = lane >> 2, t2 = (lane & 3) * 2;

#pragma unroll
    for (int ma = 0; ma < 3; ma++) {
#pragma unroll
        for (int na = 0; na < 4; na++) {
            int n = n0 + nw + na * 8 + t2;
            float2 b2 = make_float2(0.f, 0.f);
            if (layer > 0) b2 = *(const float2*)(bias + n);
#pragma unroll
            for (int hh = 0; hh < 2; hh++) {
                int m = m0 + mw + ma * 16 + g + hh * 8;
                float cx = acc[ma][na][hh * 2], cy = acc[ma][na][hh * 2 + 1];
                float2 y;
                if (layer > 0) {
                    float2 xo = *(const float2*)(Xprev + (size_t)m * 1024 + n);
                    y.x = xo.x + hv * fmaxf(cx + b2.x, 0.f);
                    y.y = xo.y + hv * fmaxf(cy + b2.y, 0.f);
                } else {
                    y.x = cx; y.y = cy;
                }
                if (m % 3 == 1) {          // S channel: no projection
                    *(float2*)(PL + (size_t)m * 1024 + n) = y;
                    __half2 h2;
                    h2.x = __float2half_rn(y.x);
                    h2.y = __float2half_rn(y.y);
                    *(__half2*)(&g_hX[opar][(size_t)m * 1024 + n]) = h2;
                } else {                   // U/V channels: polar input only
                    *(float2*)(g_Y + (size_t)m * 1024 + n) = y;
                }
            }
        }
    }
}

// ---------------- polar projection (restructured Newton-Schulz) --------------
// All iterates are polynomials in G -> symmetric & commuting. Iter 0 collapses
// to Y1 = ca*Y + cb*Y^2, Z1 = ca*I + cb*Y (one matmul). Later iters:
// M = Z*Y; Ynew = ca*Y + cb*(Y*M); Znew = ca*Z + cb*(Z*M) (shared M reads).
// Final iteration skips the (dead) Y update.
#define PNW 4
__global__ __launch_bounds__(128) void polar_kernel(int plane, int nspecial,
                                                    int nclassic, float ca_s,
                                                    float cb_s, int opar) {
    __shared__ float AsP[PNW][16][68];
    __shared__ float MsP[PNW][3][16][20];

    int w = threadIdx.x >> 5, lane = threadIdx.x & 31;
    int idx = blockIdx.x * PNW + w;
    int b = idx >> 1, ch = (idx & 1) * 2;

    const float* src = g_Y + (size_t)(b * 3 + ch) * 1024;
    size_t doff = (size_t)(b * 3 + ch) * 1024;
    float* dst = g_xt + (size_t)plane * PLANE + doff;

    float (*A)[68]  = AsP[w];
    float (*Ym)[20] = MsP[w][0];
    float (*Zm)[20] = MsP[w][1];
    float (*Tm)[20] = MsP[w][2];

    int r0 = lane * 2;
    float a0r[16], a1r[16];            // own two A rows kept in registers
#pragma unroll
    for (int qq = 0; qq < 4; qq++) {
        float4 v0 = *(const float4*)(src + r0 * 16 + qq * 4);
        float4 v1 = *(const float4*)(src + (r0 + 1) * 16 + qq * 4);
        a0r[qq * 4 + 0] = v0.x; a0r[qq * 4 + 1] = v0.y;
        a0r[qq * 4 + 2] = v0.z; a0r[qq * 4 + 3] = v0.w;
        a1r[qq * 4 + 0] = v1.x; a1r[qq * 4 + 1] = v1.y;
        a1r[qq * 4 + 2] = v1.z; a1r[qq * 4 + 3] = v1.w;
        A[qq * 4 + 0][r0] = v0.x; A[qq * 4 + 1][r0] = v0.y;
        A[qq * 4 + 2][r0] = v0.z; A[qq * 4 + 3][r0] = v0.w;
        A[qq * 4 + 0][r0 + 1] = v1.x; A[qq * 4 + 1][r0 + 1] = v1.y;
        A[qq * 4 + 2][r0 + 1] = v1.z; A[qq * 4 + 3][r0 + 1] = v1.w;
    }
    __syncwarp();

    int i0 = (lane >> 2) * 2, j0 = (lane & 3) * 4;
    float g0[4] = {0, 0, 0, 0}, g1[4] = {0, 0, 0, 0};
#pragma unroll
    for (int r = 0; r < 64; r += 4) {
        float4 a0 = *(const float4*)&A[i0][r];
        float4 a1 = *(const float4*)&A[i0 + 1][r];
#pragma unroll
        for (int t = 0; t < 4; t++) {
            float4 aj = *(const float4*)&A[j0 + t][r];
            g0[t] += a0.x * aj.x + a0.y * aj.y + a0.z * aj.z + a0.w * aj.w;
            g1[t] += a1.x * aj.x + a1.y * aj.y + a1.z * aj.z + a1.w * aj.w;
        }
    }
    *(float4*)&Ym[i0][j0]     = make_float4(g0[0], g0[1], g0[2], g0[3]);
    *(float4*)&Ym[i0 + 1][j0] = make_float4(g1[0], g1[1], g1[2], g1[3]);
    __syncwarp();

    float rs = 0.f;
    if (lane < 16) {
#pragma unroll
        for (int j = 0; j < 16; j++) rs += fabsf(Ym[lane][j]);
    }
#pragma unroll
    for (int off = 16; off; off >>= 1)
        rs = fmaxf(rs, __shfl_xor_sync(0xffffffffu, rs, off));
    float invs = 1.0f / rs;

#pragma unroll
    for (int t = 0; t < 4; t++) { g0[t] *= invs; g1[t] *= invs; }
    *(float4*)&Ym[i0][j0]     = make_float4(g0[0], g0[1], g0[2], g0[3]);
    *(float4*)&Ym[i0 + 1][j0] = make_float4(g1[0], g1[1], g1[2], g1[3]);
    __syncwarp();

    int ntot = nspecial + nclassic;

    // ---- iteration 0 (Z0 = I): S = Y*Y; Y1 = ca*Y + cb*S; Z1 = ca*I + cb*Y
    {
        float ca = (0 < nspecial) ? ca_s : 1.5f;
        float cb = (0 < nspecial) ? cb_s : -0.5f;
        float s0[4] = {0, 0, 0, 0}, s1[4] = {0, 0, 0, 0};
#pragma unroll
        for (int k = 0; k < 16; k++) {
            float ya = Ym[i0][k], yb = Ym[i0 + 1][k];
            float4 y4 = *(const float4*)&Ym[k][j0];
            s0[0] += ya * y4.x; s0[1] += ya * y4.y; s0[2] += ya * y4.z; s0[3] += ya * y4.w;
            s1[0] += yb * y4.x; s1[1] += yb * y4.y; s1[2] += yb * y4.z; s1[3] += yb * y4.w;
        }
        float4 yc0 = *(const float4*)&Ym[i0][j0];
        float4 yc1 = *(const float4*)&Ym[i0 + 1][j0];
        __syncwarp();
        *(float4*)&Ym[i0][j0] = make_float4(ca * yc0.x + cb * s0[0], ca * yc0.y + cb * s0[1],
                                            ca * yc0.z + cb * s0[2], ca * yc0.w + cb * s0[3]);
        *(float4*)&Ym[i0 + 1][j0] = make_float4(ca * yc1.x + cb * s1[0], ca * yc1.y + cb * s1[1],
                                                ca * yc1.z + cb * s1[2], ca * yc1.w + cb * s1[3]);
        *(float4*)&Zm[i0][j0] = make_float4(
            (i0 == j0 ? ca : 0.f) + cb * yc0.x, (i0 == j0 + 1 ? ca : 0.f) + cb * yc0.y,
            (i0 == j0 + 2 ? ca : 0.f) + cb * yc0.z, (i0 == j0 + 3 ? ca : 0.f) + cb * yc0.w);
        *(float4*)&Zm[i0 + 1][j0] = make_float4(
            (i0 + 1 == j0 ? ca : 0.f) + cb * yc1.x, (i0 + 1 == j0 + 1 ? ca : 0.f) + cb * yc1.y,
            (i0 + 1 == j0 + 2 ? ca : 0.f) + cb * yc1.z, (i0 + 1 == j0 + 3 ? ca : 0.f) + cb * yc1.w);
        __syncwarp();
    }

    for (int it = 1; it < ntot; it++) {
        float ca = (it < nspecial) ? ca_s : 1.5f;
        float cb = (it < nspecial) ? cb_s : -0.5f;
        bool lastit = (it == ntot - 1);

        // M = Z*Y -> Tm (raw)
        float t0[4] = {0, 0, 0, 0}, t1[4] = {0, 0, 0, 0};
#pragma unroll
        for (int k = 0; k < 16; k++) {
            float z0 = Zm[i0][k], z1 = Zm[i0 + 1][k];
            float4 y4 = *(const float4*)&Ym[k][j0];
            t0[0] += z0 * y4.x; t0[1] += z0 * y4.y; t0[2] += z0 * y4.z; t0[3] += z0 * y4.w;
            t1[0] += z1 * y4.x; t1[1] += z1 * y4.y; t1[2] += z1 * y4.z; t1[3] += z1 * y4.w;
        }
        *(float4*)&Tm[i0][j0]     = make_float4(t0[0], t0[1], t0[2], t0[3]);
        *(float4*)&Tm[i0 + 1][j0] = make_float4(t1[0], t1[1], t1[2], t1[3]);
        __syncwarp();

        // Ynew = ca*Y + cb*(Y*M); Znew = ca*Z + cb*(Z*M)  (shared M float4 reads)
        float yn0[4] = {0, 0, 0, 0}, yn1[4] = {0, 0, 0, 0};
        float zn0[4] = {0, 0, 0, 0}, zn1[4] = {0, 0, 0, 0};
#pragma unroll
        for (int k = 0; k < 16; k++) {
            float4 m4 = *(const float4*)&Tm[k][j0];
            float za = Zm[i0][k], zb = Zm[i0 + 1][k];
            zn0[0] += za * m4.x; zn0[1] += za * m4.y; zn0[2] += za * m4.z; zn0[3] += za * m4.w;
            zn1[0] += zb * m4.x; zn1[1] += zb * m4.y; zn1[2] += zb * m4.z; zn1[3] += zb * m4.w;
            if (!lastit) {
                float ya = Ym[i0][k], yb = Ym[i0 + 1][k];
                yn0[0] += ya * m4.x; yn0[1] += ya * m4.y; yn0[2] += ya * m4.z; yn0[3] += ya * m4.w;
                yn1[0] += yb * m4.x; yn1[1] += yb * m4.y; yn1[2] += yb * m4.z; yn1[3] += yb * m4.w;
            }
        }
        float4 zc0 = *(const float4*)&Zm[i0][j0];
        float4 zc1 = *(const float4*)&Zm[i0 + 1][j0];
        float4 yc0, yc1;
        if (!lastit) {
            yc0 = *(const float4*)&Ym[i0][j0];
            yc1 = *(const float4*)&Ym[i0 + 1][j0];
        }
        __syncwarp();
        *(float4*)&Zm[i0][j0] = make_float4(ca * zc0.x + cb * zn0[0], ca * zc0.y + cb * zn0[1],
                                            ca * zc0.z + cb * zn0[2], ca * zc0.w + cb * zn0[3]);
        *(float4*)&Zm[i0 + 1][j0] = make_float4(ca * zc1.x + cb * zn1[0], ca * zc1.y + cb * zn1[1],
                                                ca * zc1.z + cb * zn1[2], ca * zc1.w + cb * zn1[3]);
        if (!lastit) {
            *(float4*)&Ym[i0][j0] = make_float4(ca * yc0.x + cb * yn0[0], ca * yc0.y + cb * yn0[1],
                                                ca * yc0.z + cb * yn0[2], ca * yc0.w + cb * yn0[3]);
            *(float4*)&Ym[i0 + 1][j0] = make_float4(ca * yc1.x + cb * yn1[0], ca * yc1.y + cb * yn1[1],
                                                    ca * yc1.z + cb * yn1[2], ca * yc1.w + cb * yn1[3]);
        }
        __syncwarp();
    }

    // U = A * Z * s^(-1/2); own A rows come from registers
    float isq = rsqrtf(rs);
    float u0[16], u1[16];
#pragma unroll
    for (int c = 0; c < 16; c++) { u0[c] = 0.f; u1[c] = 0.f; }
#pragma unroll
    for (int k = 0; k < 16; k++) {
        float a0 = a0r[k], a1 = a1r[k];
#pragma unroll
        for (int cq = 0; cq < 4; cq++) {
            float4 z4 = *(const float4*)&Zm[k][cq * 4];
            u0[cq * 4 + 0] += a0 * z4.x; u0[cq * 4 + 1] += a0 * z4.y;
            u0[cq * 4 + 2] += a0 * z4.z; u0[cq * 4 + 3] += a0 * z4.w;
            u1[cq * 4 + 0] += a1 * z4.x; u1[cq * 4 + 1] += a1 * z4.y;
            u1[cq * 4 + 2] += a1 * z4.z; u1[cq * 4 + 3] += a1 * z4.w;
        }
    }
#pragma unroll
    for (int c = 0; c < 16; c++) { u0[c] *= isq; u1[c] *= isq; }

    // fp32 U out
#pragma unroll
    for (int cq = 0; cq < 4; cq++) {
        *(float4*)(dst + r0 * 16 + cq * 4) =
            make_float4(u0[cq * 4], u0[cq * 4 + 1], u0[cq * 4 + 2], u0[cq * 4 + 3]);
        *(float4*)(dst + (r0 + 1) * 16 + cq * 4) =
            make_float4(u1[cq * 4], u1[cq * 4 + 1], u1[cq * 4 + 2], u1[cq * 4 + 3]);
    }

    // fp16 out: pack via smem for coalesced writes
    uint32_t phi[16];
#pragma unroll
    for (int row2 = 0; row2 < 2; row2++) {
        float* u = row2 ? u1 : u0;
#pragma unroll
        for (int cq = 0; cq < 8; cq++) {
            __half2 hp2;
            hp2.x = __float2half_rn(u[2 * cq]);
            hp2.y = __float2half_rn(u[2 * cq + 1]);
            phi[row2 * 8 + cq] = *(uint32_t*)&hp2;
        }
    }
    __syncwarp();
    uint32_t* pk = (uint32_t*)&A[0][0];
#pragma unroll
    for (int row2 = 0; row2 < 2; row2++)
#pragma unroll
        for (int cq = 0; cq < 8; cq++) pk[(r0 + row2) * 8 + cq] = phi[row2 * 8 + cq];
    __syncwarp();
    {
        uint32_t* gd = (uint32_t*)(g_hX[opar] + doff);
#pragma unroll
        for (int i = 0; i < 16; i++) gd[lane + 32 * i] = pk[lane + 32 * i];
    }
}

// ---------------- X_transformed transpose ------------------------------------
__global__ void xt_kernel(float* __restrict__ out) {
    __shared__ float tile[256][18];
    int base = blockIdx.x * 256;
    int tid = threadIdx.x;
#pragma unroll
    for (int l = 0; l < 17; l++)
        tile[tid][l] = g_xt[(size_t)l * PLANE + base + tid];
    __syncthreads();
    float* o = out + (size_t)base * 17;
    for (int i = tid; i < 256 * 17; i += 256)
        o[i] = tile[i / 17][i % 17];
}

// ---------------- reconstruct + classify + softmax ----------------------------
__global__ __launch_bounds__(128) void classify_kernel(
    const float* __restrict__ Wc, const float* __restrict__ bc,
    float* __restrict__ out, int off_log)
{
    __shared__ float sU[1024], sS[256], sV[1024], sT[1024];
    __shared__ float sZ[4096];
    __shared__ float red[10 * 136];
    __shared__ float slog[10];

    int b = blockIdx.x, tid = threadIdx.x;
    const float* base = g_xt + (size_t)16 * PLANE + (size_t)b * 3 * 1024;

    for (int i = tid; i < 1024; i += 128) { sU[i] = base[i]; sV[i] = base[2048 + i]; }
    for (int i = tid; i < 256; i += 128) sS[i] = base[1024 + i];
    __syncthreads();

    for (int e = tid; e < 1024; e += 128) {
        int r = e >> 4, c = e & 15;
        float sum = 0.f;
#pragma unroll
        for (int k = 0; k < 16; k++) sum += sU[r * 16 + k] * sS[k * 16 + c];
        sT[e] = sum;
    }
    __syncthreads();

    for (int e = tid; e < 4096; e += 128) {
        int r = e >> 6, qn = e & 63;
        float sum = 0.f;
#pragma unroll
        for (int c = 0; c < 16; c++) sum += sT[r * 16 + c] * sV[qn * 16 + c];
        sZ[e] = sum;
    }
    __syncthreads();

    float acc[10];
#pragma unroll
    for (int n = 0; n < 10; n++) acc[n] = 0.f;
    for (int e = tid; e < 4096; e += 128) {
        float z = sZ[e];
#pragma unroll
        for (int n = 0; n < 10; n++) acc[n] += z * Wc[n * 4096 + e];
    }
#pragma unroll
    for (int n = 0; n < 10; n++) red[n * 136 + tid] = acc[n];
    __syncthreads();
    if (tid < 10) {
        float s = bc[tid];
        for (int j = 0; j < 128; j++) s += red[tid * 136 + j];
        slog[tid] = s;
    }
    __syncthreads();
    if (tid == 0) {
        float mx = slog[0];
        for (int n = 1; n < 10; n++) mx = fmaxf(mx, slog[n]);
        float ex[10]; float se = 0.f;
        for (int n = 0; n < 10; n++) { ex[n] = expf(slog[n] - mx); se += ex[n]; }
        float inv = 1.f / se;
        for (int n = 0; n < 10; n++) {
            out[b * 10 + n] = ex[n] * inv;
            if (off_log >= 0) out[off_log + b * 10 + n] = slog[n];
        }
    }
}

// ---------------- launch ------------------------------------------------------
extern "C" void kernel_launch(void* const* d_in, const int* in_sizes, int n_in,
                              void* d_out, int out_size) {
    const float* X  = (const float*)d_in[0];
    const float* h  = (const float*)d_in[1];
    const float* W0 = (const float*)d_in[2];
    const float* Ws = (const float*)d_in[3];
    const float* bs = (const float*)d_in[4];
    const float* Wc = (const float*)d_in[5];
    const float* bc = (const float*)d_in[6];
    float* out = (float*)d_out;

    int off_log = -1, off_xt = -1;
    if (out_size >= 10240 + 10240 + 53477376) { off_log = 10240; off_xt = 20480; }
    else if (out_size == 10240 + 53477376)    { off_xt = 10240; }
    else if (out_size >= 20480)               { off_log = 10240; }

    cudaFuncSetAttribute(tgemm_kernel, cudaFuncAttributeMaxDynamicSharedMemorySize,
                         SMEM_TOTAL_G);

    wconv_kernel<<<WELEMS / 256, 256>>>(W0, Ws);
    prep_kernel<<<PLANE / 256, 256>>>(X);

    tgemm_kernel<<<256, 256, SMEM_TOTAL_G>>>(nullptr, h, 0);
    polar_kernel<<<512, 128>>>(0, 4, 5, 2.4f, -1.4f, 1);   // layer 0: 4 agg + 5 classic
    for (int l = 1; l <= 16; l++) {
        tgemm_kernel<<<256, 256, SMEM_TOTAL_G>>>(bs + (size_t)(l - 1) * 1024, h, l);
        polar_kernel<<<512, 128>>>(l, 1, 2, 1.9f, -0.9f, (l + 1) & 1);  // 1 tuned + 2 classic
    }

    if (off_xt >= 0)
        xt_kernel<<<PLANE / 256, 256>>>(out + off_xt);
    classify_kernel<<<1024, 128>>>(Wc, bc, out, off_log);
}